// round 15
// baseline (speedup 1.0000x reference)
#include <cuda_runtime.h>
#include <cuda_bf16.h>
#include <math.h>

#define BATCH 512
#define DIN   768
#define HID   256
#define NGEN  4095
#define NGPAD 4096
#define QDIM  64
#define NOBS  15
#define CSTR  65   // padded row stride (float2) for Cbuf

typedef unsigned long long ull;

// ---------------- scratch (no allocation allowed) ----------------
__device__ float g_hidden[BATCH * HID];
__device__ float g_theta[BATCH * NGPAD];
__device__ float g_hid2[BATCH * HID];
__device__ float2 g_Hw[NOBS * 16];

__device__ __constant__ int cPA[NOBS] = {0,0,0,0,0,1,1,1,1,2,2,2,3,3,4};
__device__ __constant__ int cPB[NOBS] = {1,2,3,4,5,2,3,4,5,3,4,5,4,5,5};

// ---- compile-time forward table: slot n=xm*64+zm -> (theta index m)*4 + phase code ----
struct PermTab {
    unsigned short v[4096];
    constexpr PermTab() : v{} {
        v[0] = 0;
        for (int m = 0; m < 4095; m++) {
            int f = m + 1, xm = 0, zm = 0;
            for (int p = 0; p < 6; p++) {
                int c  = (f >> (2 * p)) & 3;
                int zb = c >> 1;
                int xb = (c & 1) ^ zb;
                xm |= xb << p;
                zm |= zb << p;
            }
            int w = xm & zm, ny = 0;
            for (int p = 0; p < 6; p++) ny += (w >> p) & 1;
            ny &= 3;
            v[xm * 64 + zm] = (unsigned short)(m * 4 + ny);
        }
    }
};
__device__ const PermTab g_ptab = PermTab();

// ---------------- packed f32x2 helpers ----------------
__device__ __forceinline__ void ffma2(ull& d, ull a, ull b) {
    asm("fma.rn.f32x2 %0, %1, %2, %0;" : "+l"(d) : "l"(a), "l"(b));
}
__device__ __forceinline__ ull pack2(float x, float y) {
    ull r; asm("mov.b64 %0, {%1, %2};" : "=l"(r) : "f"(x), "f"(y)); return r;
}
__device__ __forceinline__ void unpack2(ull v, float& x, float& y) {
    asm("mov.b64 {%0, %1}, %2;" : "=f"(x), "=f"(y) : "l"(v));
}

// ================= prep: observable Hermitians -> g_Hw (idempotent; shifts ncu slot) =================
__global__ void prep_kernel(const float* __restrict__ Aoff,
                            const float* __restrict__ Boff,
                            const float* __restrict__ Ddiag)
{
    int e = threadIdx.x;
    if (e < NOBS * 16) {
        int w = e >> 4, ee = e & 15, li = ee >> 2, k = ee & 3;
        float2 v;
        if (li == k)      { v.x = (li < 3) ? 2.f * Ddiag[w * 4 + li + 1] : 0.f; v.y = 0.f; }
        else if (li > k)  { int c = li * (li - 1) / 2 + k; v.x = Aoff[w * 6 + c]; v.y =  Boff[w * 6 + c]; }
        else              { int c = k * (k - 1) / 2 + li; v.x = Aoff[w * 6 + c]; v.y = -Boff[w * 6 + c]; }
        g_Hw[e] = v;
    }
}

// ================= gemm1: 32x32 tiles, k-tile 32 (R14) =================
__global__ __launch_bounds__(256) void gemm1_kernel(const float* __restrict__ A,
                                                    const float* __restrict__ B,
                                                    const float* __restrict__ bias)
{
    const int K = DIN, N = HID;
    __shared__ float As[32][32];
    __shared__ float Bs[32][32];

    int t = threadIdx.x;
    int nBase = blockIdx.x * 32;
    int mBase = blockIdx.y * 32;
    int tx = t & 15, ty = t >> 4;
    int ar = t >> 3, ak = (t & 7) * 4;
    int br = t >> 3, bc = (t & 7) * 4;

    float acc00 = 0.f, acc01 = 0.f, acc10 = 0.f, acc11 = 0.f;

    float4 aP = *reinterpret_cast<const float4*>(A + (size_t)(mBase + ar) * K + ak);
    float4 bP = *reinterpret_cast<const float4*>(B + (size_t)br * N + nBase + bc);

    for (int kt = 0; kt < K; kt += 32) {
        As[ak][ar] = aP.x; As[ak + 1][ar] = aP.y; As[ak + 2][ar] = aP.z; As[ak + 3][ar] = aP.w;
        *reinterpret_cast<float4*>(&Bs[br][bc]) = bP;
        __syncthreads();
        if (kt + 32 < K) {
            aP = *reinterpret_cast<const float4*>(A + (size_t)(mBase + ar) * K + kt + 32 + ak);
            bP = *reinterpret_cast<const float4*>(B + (size_t)(kt + 32 + br) * N + nBase + bc);
        }
#pragma unroll
        for (int k = 0; k < 32; k++) {
            float a0 = As[k][ty * 2], a1 = As[k][ty * 2 + 1];
            float b0 = Bs[k][tx * 2], b1 = Bs[k][tx * 2 + 1];
            acc00 += a0 * b0; acc01 += a0 * b1;
            acc10 += a1 * b0; acc11 += a1 * b1;
        }
        __syncthreads();
    }

    int m0 = mBase + ty * 2, n0 = nBase + tx * 2;
    float bb0 = bias[n0], bb1 = bias[n0 + 1];
    float v;
    v = acc00 + bb0; g_hidden[(size_t)m0 * HID + n0]           = v / (1.f + expf(-v));
    v = acc01 + bb1; g_hidden[(size_t)m0 * HID + n0 + 1]       = v / (1.f + expf(-v));
    v = acc10 + bb0; g_hidden[(size_t)(m0 + 1) * HID + n0]     = v / (1.f + expf(-v));
    v = acc11 + bb1; g_hidden[(size_t)(m0 + 1) * HID + n0 + 1] = v / (1.f + expf(-v));
}

// ================= final gemm: 32x32 tiles, k-tile 32 (R14) =================
__global__ __launch_bounds__(256) void gemmF_kernel(const float* __restrict__ B,
                                                    const float* __restrict__ bias,
                                                    float* __restrict__ Cout)
{
    const int K = HID, N = 512;
    const float* __restrict__ A = g_hid2;
    __shared__ float As[32][32];
    __shared__ float Bs[32][32];

    int t = threadIdx.x;
    int nBase = blockIdx.x * 32;
    int mBase = blockIdx.y * 32;
    int tx = t & 15, ty = t >> 4;
    int ar = t >> 3, ak = (t & 7) * 4;
    int br = t >> 3, bc = (t & 7) * 4;

    float acc00 = 0.f, acc01 = 0.f, acc10 = 0.f, acc11 = 0.f;

    float4 aP = *reinterpret_cast<const float4*>(A + (size_t)(mBase + ar) * K + ak);
    float4 bP = *reinterpret_cast<const float4*>(B + (size_t)br * N + nBase + bc);

    for (int kt = 0; kt < K; kt += 32) {
        As[ak][ar] = aP.x; As[ak + 1][ar] = aP.y; As[ak + 2][ar] = aP.z; As[ak + 3][ar] = aP.w;
        *reinterpret_cast<float4*>(&Bs[br][bc]) = bP;
        __syncthreads();
        if (kt + 32 < K) {
            aP = *reinterpret_cast<const float4*>(A + (size_t)(mBase + ar) * K + kt + 32 + ak);
            bP = *reinterpret_cast<const float4*>(B + (size_t)(kt + 32 + br) * N + nBase + bc);
        }
#pragma unroll
        for (int k = 0; k < 32; k++) {
            float a0 = As[k][ty * 2], a1 = As[k][ty * 2 + 1];
            float b0 = Bs[k][tx * 2], b1 = Bs[k][tx * 2 + 1];
            acc00 += a0 * b0; acc01 += a0 * b1;
            acc10 += a1 * b0; acc11 += a1 * b1;
        }
        __syncthreads();
    }

    int m0 = mBase + ty * 2, n0 = nBase + tx * 2;
    float bb0 = bias[n0], bb1 = bias[n0 + 1];
    Cout[(size_t)m0 * N + n0]           = acc00 + bb0;
    Cout[(size_t)m0 * N + n0 + 1]       = acc01 + bb1;
    Cout[(size_t)(m0 + 1) * N + n0]     = acc10 + bb0;
    Cout[(size_t)(m0 + 1) * N + n0 + 1] = acc11 + bb1;
}

// ================= gemm2: 64x64 tiles -> 512 blocks, single wave at 4 blocks/SM =================
template<int M, int Nact, int Npad, int K>
__global__ __launch_bounds__(256, 4) void gemm2_64(const float* __restrict__ B,
                                                   const float* __restrict__ bias)
{
    const float* __restrict__ A = g_hidden;
    float* __restrict__ C       = g_theta;

    __shared__ float As[16][64];     // [k][m]
    __shared__ ull   Bsd[16][64];    // [k][c*16 + tx] = (b,b) for col n = tx*4 + c

    int tid   = threadIdx.x;
    int nBase = blockIdx.x * 64;
    int mBase = blockIdx.y * 64;
    int tx = tid & 15;               // col group: cols tx*4 .. tx*4+3
    int ty = tid >> 4;               // row group: rows ty*4 .. ty*4+3
    int arow = tid >> 2;             // 0..63
    int acol = (tid & 3) * 4;        // 0,4,8,12
    int brow = tid >> 4;             // 0..15
    int bcol = (tid & 15) * 4;       // 0..60

    const bool nfull = (nBase + 64) <= Nact;

    ull acc[2][4];
#pragma unroll
    for (int i = 0; i < 2; i++)
#pragma unroll
        for (int j = 0; j < 4; j++) acc[i][j] = 0ull;

    float4 aP = *reinterpret_cast<const float4*>(A + (size_t)(mBase + arow) * K + acol);
    float bP[4];
    {
        const float* Brow = B + (size_t)brow * Nact + nBase + bcol;
#pragma unroll
        for (int u = 0; u < 4; u++)
            bP[u] = (nfull || (nBase + bcol + u) < Nact) ? Brow[u] : 0.f;
    }

    for (int kt = 0; kt < K; kt += 16) {
        As[acol + 0][arow] = aP.x;
        As[acol + 1][arow] = aP.y;
        As[acol + 2][arow] = aP.z;
        As[acol + 3][arow] = aP.w;
#pragma unroll
        for (int u = 0; u < 4; u++)
            Bsd[brow][u * 16 + (tid & 15)] = pack2(bP[u], bP[u]);
        __syncthreads();

        if (kt + 16 < K) {
            aP = *reinterpret_cast<const float4*>(A + (size_t)(mBase + arow) * K + kt + 16 + acol);
            const float* Brow = B + (size_t)(kt + 16 + brow) * Nact + nBase + bcol;
#pragma unroll
            for (int u = 0; u < 4; u++)
                bP[u] = (nfull || (nBase + bcol + u) < Nact) ? Brow[u] : 0.f;
        }

#pragma unroll
        for (int k = 0; k < 16; k++) {
            ull ap0 = *reinterpret_cast<const ull*>(&As[k][ty * 4 + 0]);
            ull ap1 = *reinterpret_cast<const ull*>(&As[k][ty * 4 + 2]);
#pragma unroll
            for (int c = 0; c < 4; c++) {
                ull bd = Bsd[k][c * 16 + tx];
                ffma2(acc[0][c], ap0, bd);
                ffma2(acc[1][c], ap1, bd);
            }
        }
        __syncthreads();
    }

#pragma unroll
    for (int rp = 0; rp < 2; rp++) {
        int m0 = mBase + ty * 4 + 2 * rp;
#pragma unroll
        for (int c = 0; c < 4; c++) {
            int n = nBase + tx * 4 + c;
            float v0, v1;
            unpack2(acc[rp][c], v0, v1);
            float bb = (n < Nact) ? bias[n] : 0.f;
            C[(size_t)m0 * Npad + n]       = v0 + bb;
            C[(size_t)(m0 + 1) * Npad + n] = v1 + bb;
        }
    }
}

// ================= cheby: 256 threads/item, register WHT (R14) =================
__global__ void __launch_bounds__(256) cheby_kernel(const float* __restrict__ Wv1,
                                                    const float* __restrict__ bv1)
{
    int b = blockIdx.x;
    int t = threadIdx.x;
    int lane = t & 31, wid = t >> 5;

    __shared__ __align__(16) float2 Cbuf[CSTR * 64];
    __shared__ __align__(16) float4 VRI[2][32];
    __shared__ float PRs[64], PIs[64];
    __shared__ float2 Jc[60];
    __shared__ float2 Hw[NOBS * 16];
    __shared__ float  qsm[16];
    __shared__ float  redf[8];

    const float* __restrict__ th = g_theta + (size_t)b * NGPAD;

    // ---- phase 1: build C[x][z] slice in registers ----
    {
        int x = t >> 2, zq = t & 3;
        float2 c[16];
        int slot0 = x * 64 + 16 * zq;
#pragma unroll
        for (int zi = 0; zi < 16; zi++) {
            int e = g_ptab.v[slot0 + zi];
            int m = e >> 2, code = e & 3;
            float tv = th[m];
            float2 v = make_float2(0.f, 0.f);
            if      (code == 0) v.x =  tv;
            else if (code == 1) v.y = -tv;
            else if (code == 2) v.x = -tv;
            else                v.y =  tv;
            c[zi] = v;
        }
        if (slot0 == 0) { c[0].x = 0.f; c[0].y = 0.f; }

#pragma unroll
        for (int st = 1; st <= 8; st <<= 1) {
#pragma unroll
            for (int i = 0; i < 16; i++) {
                if (!(i & st)) {
                    float2 a = c[i], bb = c[i + st];
                    c[i]      = make_float2(a.x + bb.x, a.y + bb.y);
                    c[i + st] = make_float2(a.x - bb.x, a.y - bb.y);
                }
            }
        }
        {
            float s = (zq & 1) ? -1.f : 1.f;
#pragma unroll
            for (int i = 0; i < 16; i++) {
                float pr = __shfl_xor_sync(0xffffffffu, c[i].x, 1);
                float pi = __shfl_xor_sync(0xffffffffu, c[i].y, 1);
                c[i].x = fmaf(s, c[i].x, pr);
                c[i].y = fmaf(s, c[i].y, pi);
            }
            s = (zq & 2) ? -1.f : 1.f;
#pragma unroll
            for (int i = 0; i < 16; i++) {
                float pr = __shfl_xor_sync(0xffffffffu, c[i].x, 2);
                float pi = __shfl_xor_sync(0xffffffffu, c[i].y, 2);
                c[i].x = fmaf(s, c[i].x, pr);
                c[i].y = fmaf(s, c[i].y, pi);
            }
        }
        float2* dst = Cbuf + x * CSTR + 16 * zq;
#pragma unroll
        for (int i = 0; i < 16; i++) dst[i] = c[i];
    }
    for (int e = t; e < NOBS * 16; e += 256) Hw[e] = g_Hw[e];
    __syncthreads();

    // ---- phase 2: extract my quarter-row; H[r][j] = C[r^j][r] ----
    int r = t >> 2, qd = t & 3;
    ull hre[8], him[8];
    float frob = 0.f;
    int jbase = 16 * qd;
#pragma unroll
    for (int j2 = 0; j2 < 8; j2++) {
        int j0 = jbase + 2 * j2;
        float2 v0 = Cbuf[(r ^ j0) * CSTR + r];
        float2 v1 = Cbuf[(r ^ (j0 + 1)) * CSTR + r];
        hre[j2] = pack2(v0.x, v1.x);
        him[j2] = pack2(v0.y, v1.y);
        frob += v0.x * v0.x + v0.y * v0.y + v1.x * v1.x + v1.y * v1.y;
    }
#pragma unroll
    for (int o = 16; o; o >>= 1) frob += __shfl_xor_sync(0xffffffffu, frob, o);
    __syncthreads();
    if (lane == 0) redf[wid] = frob;
    __syncthreads();
    float frobT = 0.f;
#pragma unroll
    for (int i = 0; i < 8; i++) frobT += redf[i];

    float lam_safe = fmaxf(1.0f, 0.31f * sqrtf(frobT) + 0.4f);
    int KC = min((int)ceilf(lam_safe) + 9, 57);

    if (t == 0) {
        float* farr = reinterpret_cast<float*>(Cbuf);
        int M = KC + 6;
        float fkp1 = 0.f, fk = 1e-12f;
        farr[M] = fk;
        float twoinv = 2.f / lam_safe;
        for (int k = M; k >= 1; k--) {
            float fkm1 = fmaf((float)k * twoinv, fk, -fkp1);
            farr[k - 1] = fkm1;
            fkp1 = fk; fk = fkm1;
        }
        float s = farr[0];
        for (int k = 2; k <= M; k += 2) s += 2.f * farr[k];
        float invs = 1.f / s;
        for (int k = 0; k <= KC; k++) {
            float J = farr[k] * invs;
            float w = (k == 0) ? 1.f : 2.f;
            float cr = 0.f, ci = 0.f;
            switch (k & 3) {
                case 0: cr =  w * J; break;
                case 1: ci =  w * J; break;
                case 2: cr = -w * J; break;
                case 3: ci = -w * J; break;
            }
            Jc[k].x = cr; Jc[k].y = ci;
        }
    }
    __syncthreads();
    float invl = 1.f / lam_safe;

    float t1r = 0.f, t1i = 0.f;
    if (qd == 0) {
        float a, b2, c, d;
        unpack2(hre[0], a, b2);
        unpack2(him[0], c, d);
        t1r = a * invl; t1i = c * invl;
        (void)b2; (void)d;
    }
    t1r = __shfl_sync(0xffffffffu, t1r, lane & ~3);
    t1i = __shfl_sync(0xffffffffu, t1i, lane & ~3);

    float tkm1r = (r == 0) ? 1.f : 0.f, tkm1i = 0.f;
    float tkr = t1r, tki = t1i;
    float2 c1 = Jc[1];
    float psr  = ((r == 0) ? Jc[0].x : 0.f) + c1.x * tkr - c1.y * tki;
    float psii = c1.x * tki + c1.y * tkr;
    int qq = r >> 1;
    int wp = 4 * (qq & 7) + (qq >> 3);
    if (qd == 0) {
        float* vf = reinterpret_cast<float*>(&VRI[0][wp]);
        vf[r & 1]       = tkr;
        vf[2 + (r & 1)] = tki;
    }
    __syncthreads();

    int cur = 0;
    float two_invl = 2.f * invl;
    for (int k = 2; k <= KC; k++) {
        const float4* Vb = VRI[cur];
        ull S1 = 0, S2 = 0, S3 = 0, S4 = 0;
#pragma unroll
        for (int j = 0; j < 8; j++) {
            float4 vv = Vb[4 * j + qd];
            ull vr = pack2(vv.x, vv.y);
            ull vi = pack2(vv.z, vv.w);
            ffma2(S1, hre[j], vr);
            ffma2(S2, him[j], vi);
            ffma2(S3, hre[j], vi);
            ffma2(S4, him[j], vr);
        }
        float a, b2, c, d;
        unpack2(S1, a, b2); float s1 = a + b2;
        unpack2(S2, a, b2); float s2 = a + b2;
        unpack2(S3, a, b2); float s3 = a + b2;
        unpack2(S4, a, b2); float s4 = a + b2;
        float wr = s1 - s2, wi = s3 + s4;
        wr += __shfl_xor_sync(0xffffffffu, wr, 1);
        wi += __shfl_xor_sync(0xffffffffu, wi, 1);
        wr += __shfl_xor_sync(0xffffffffu, wr, 2);
        wi += __shfl_xor_sync(0xffffffffu, wi, 2);

        float tnr = fmaf(two_invl, wr, -tkm1r);
        float tni = fmaf(two_invl, wi, -tkm1i);
        float2 cc = Jc[k];
        psr  += cc.x * tnr - cc.y * tni;
        psii += cc.x * tni + cc.y * tnr;
        tkm1r = tkr; tkm1i = tki;
        tkr = tnr;   tki = tni;
        if (qd == 0) {
            float* vf = reinterpret_cast<float*>(&VRI[cur ^ 1][wp]);
            vf[r & 1]       = tnr;
            vf[2 + (r & 1)] = tni;
        }
        __syncthreads();
        cur ^= 1;
    }

    if (qd == 0) { PRs[r] = psr; PIs[r] = psii; }
    __syncthreads();

    float qr = 0.f;
    if (t < 60) {
        int w = t >> 2, rbase = (t & 3) * 4;
        int a = cPA[w], bq = cPB[w];
        int pa = 5 - a, pb = 5 - bq;
        for (int rr = 0; rr < 4; rr++) {
            int rj = rbase + rr;
            int ibase = 0, bitidx = 3;
#pragma unroll
            for (int q = 0; q < 6; q++) {
                if (q == a || q == bq) continue;
                ibase |= ((rj >> bitidx) & 1) << (5 - q);
                bitidx--;
            }
            float2 v[4];
#pragma unroll
            for (int k = 0; k < 4; k++) {
                int i = ibase | ((k >> 1) << pa) | ((k & 1) << pb);
                v[k] = make_float2(PRs[i], PIs[i]);
            }
#pragma unroll
            for (int li = 0; li < 4; li++)
#pragma unroll
                for (int k = 0; k < 4; k++) {
                    float2 hw = Hw[w * 16 + li * 4 + k];
                    float pr = v[li].x * v[k].x + v[li].y * v[k].y;
                    float pi = v[li].x * v[k].y - v[li].y * v[k].x;
                    qr += hw.x * pr - hw.y * pi;
                }
        }
    }
    qr += __shfl_down_sync(0xffffffffu, qr, 1);
    qr += __shfl_down_sync(0xffffffffu, qr, 2);
    if (t < 60 && (t & 3) == 0) qsm[t >> 2] = qr;
    __syncthreads();

    {
        int col = t;
        float acc = bv1[col];
#pragma unroll
        for (int w = 0; w < NOBS; w++) acc = fmaf(qsm[w], Wv1[w * HID + col], acc);
        g_hid2[(size_t)b * HID + col] = acc / (1.f + expf(-acc));
    }
}

// ---------------- launch ----------------
extern "C" void kernel_launch(void* const* d_in, const int* in_sizes, int n_in,
                              void* d_out, int out_size)
{
    const float* x    = (const float*)d_in[0];
    const float* W1   = (const float*)d_in[1];
    const float* b1   = (const float*)d_in[2];
    const float* W2   = (const float*)d_in[3];
    const float* b2   = (const float*)d_in[4];
    const float* Aoff = (const float*)d_in[5];
    const float* Boff = (const float*)d_in[6];
    const float* Ddia = (const float*)d_in[7];
    const float* Wv1  = (const float*)d_in[8];
    const float* bv1  = (const float*)d_in[9];
    const float* Wv2  = (const float*)d_in[10];
    const float* bv2  = (const float*)d_in[11];
    float* out = (float*)d_out;

    // slots 1-2: prep twice (idempotent) -> gemm2_64 lands in profiled slot 4
    prep_kernel<<<1, 256>>>(Aoff, Boff, Ddia);
    prep_kernel<<<1, 256>>>(Aoff, Boff, Ddia);
    // slot 3: hidden = silu(x @ W1 + b1)
    gemm1_kernel<<<dim3(HID / 32, BATCH / 32), 256>>>(x, W1, b1);
    // slot 4: theta = hidden @ W2 + b2  (PROFILED) — 64x64 tiles, 512 blocks
    gemm2_64<BATCH, NGEN, NGPAD, HID><<<dim3(NGPAD / 64, BATCH / 64), 256>>>(W2, b2);
    // slot 5: psi/observables/hidden2
    cheby_kernel<<<BATCH, 256>>>(Wv1, bv1);
    // slot 6: out = hid2 @ Wv2 + bv2
    gemmF_kernel<<<dim3(512 / 32, BATCH / 32), 256>>>(Wv2, bv2, out);
}

// round 16
// speedup vs baseline: 1.1419x; 1.1419x over previous
#include <cuda_runtime.h>
#include <cuda_bf16.h>
#include <math.h>

#define BATCH 512
#define DIN   768
#define HID   256
#define NGEN  4095
#define NGPAD 4096
#define QDIM  64
#define NOBS  15
#define CSTR  65   // padded row stride (float2) for Cbuf

typedef unsigned long long ull;

// ---------------- scratch (no allocation allowed) ----------------
__device__ float g_hidden[BATCH * HID];
__device__ float g_theta[BATCH * NGPAD];
__device__ float g_hid2[BATCH * HID];
__device__ float2 g_Hw[NOBS * 16];

__device__ __constant__ int cPA[NOBS] = {0,0,0,0,0,1,1,1,1,2,2,2,3,3,4};
__device__ __constant__ int cPB[NOBS] = {1,2,3,4,5,2,3,4,5,3,4,5,4,5,5};

// ---- compile-time forward table: slot n=xm*64+zm -> (theta index m)*4 + phase code ----
struct PermTab {
    unsigned short v[4096];
    constexpr PermTab() : v{} {
        v[0] = 0;
        for (int m = 0; m < 4095; m++) {
            int f = m + 1, xm = 0, zm = 0;
            for (int p = 0; p < 6; p++) {
                int c  = (f >> (2 * p)) & 3;
                int zb = c >> 1;
                int xb = (c & 1) ^ zb;
                xm |= xb << p;
                zm |= zb << p;
            }
            int w = xm & zm, ny = 0;
            for (int p = 0; p < 6; p++) ny += (w >> p) & 1;
            ny &= 3;
            v[xm * 64 + zm] = (unsigned short)(m * 4 + ny);
        }
    }
};
__device__ const PermTab g_ptab = PermTab();

// ---------------- packed f32x2 helpers ----------------
__device__ __forceinline__ void ffma2(ull& d, ull a, ull b) {
    asm("fma.rn.f32x2 %0, %1, %2, %0;" : "+l"(d) : "l"(a), "l"(b));
}
__device__ __forceinline__ ull pack2(float x, float y) {
    ull r; asm("mov.b64 %0, {%1, %2};" : "=l"(r) : "f"(x), "f"(y)); return r;
}
__device__ __forceinline__ void unpack2(ull v, float& x, float& y) {
    asm("mov.b64 {%0, %1}, %2;" : "=f"(x), "=f"(y) : "l"(v));
}

// ================= prep: observable Hermitians -> g_Hw (idempotent; shifts ncu slot) =================
__global__ void prep_kernel(const float* __restrict__ Aoff,
                            const float* __restrict__ Boff,
                            const float* __restrict__ Ddiag)
{
    int e = threadIdx.x;
    if (e < NOBS * 16) {
        int w = e >> 4, ee = e & 15, li = ee >> 2, k = ee & 3;
        float2 v;
        if (li == k)      { v.x = (li < 3) ? 2.f * Ddiag[w * 4 + li + 1] : 0.f; v.y = 0.f; }
        else if (li > k)  { int c = li * (li - 1) / 2 + k; v.x = Aoff[w * 6 + c]; v.y =  Boff[w * 6 + c]; }
        else              { int c = k * (k - 1) / 2 + li; v.x = Aoff[w * 6 + c]; v.y = -Boff[w * 6 + c]; }
        g_Hw[e] = v;
    }
}

// ================= gemm1: 32x32 tiles, k-tile 32 (R14) =================
__global__ __launch_bounds__(256) void gemm1_kernel(const float* __restrict__ A,
                                                    const float* __restrict__ B,
                                                    const float* __restrict__ bias)
{
    const int K = DIN, N = HID;
    __shared__ float As[32][32];
    __shared__ float Bs[32][32];

    int t = threadIdx.x;
    int nBase = blockIdx.x * 32;
    int mBase = blockIdx.y * 32;
    int tx = t & 15, ty = t >> 4;
    int ar = t >> 3, ak = (t & 7) * 4;
    int br = t >> 3, bc = (t & 7) * 4;

    float acc00 = 0.f, acc01 = 0.f, acc10 = 0.f, acc11 = 0.f;

    float4 aP = *reinterpret_cast<const float4*>(A + (size_t)(mBase + ar) * K + ak);
    float4 bP = *reinterpret_cast<const float4*>(B + (size_t)br * N + nBase + bc);

    for (int kt = 0; kt < K; kt += 32) {
        As[ak][ar] = aP.x; As[ak + 1][ar] = aP.y; As[ak + 2][ar] = aP.z; As[ak + 3][ar] = aP.w;
        *reinterpret_cast<float4*>(&Bs[br][bc]) = bP;
        __syncthreads();
        if (kt + 32 < K) {
            aP = *reinterpret_cast<const float4*>(A + (size_t)(mBase + ar) * K + kt + 32 + ak);
            bP = *reinterpret_cast<const float4*>(B + (size_t)(kt + 32 + br) * N + nBase + bc);
        }
#pragma unroll
        for (int k = 0; k < 32; k++) {
            float a0 = As[k][ty * 2], a1 = As[k][ty * 2 + 1];
            float b0 = Bs[k][tx * 2], b1 = Bs[k][tx * 2 + 1];
            acc00 += a0 * b0; acc01 += a0 * b1;
            acc10 += a1 * b0; acc11 += a1 * b1;
        }
        __syncthreads();
    }

    int m0 = mBase + ty * 2, n0 = nBase + tx * 2;
    float bb0 = bias[n0], bb1 = bias[n0 + 1];
    float v;
    v = acc00 + bb0; g_hidden[(size_t)m0 * HID + n0]           = v / (1.f + expf(-v));
    v = acc01 + bb1; g_hidden[(size_t)m0 * HID + n0 + 1]       = v / (1.f + expf(-v));
    v = acc10 + bb0; g_hidden[(size_t)(m0 + 1) * HID + n0]     = v / (1.f + expf(-v));
    v = acc11 + bb1; g_hidden[(size_t)(m0 + 1) * HID + n0 + 1] = v / (1.f + expf(-v));
}

// ================= final gemm: 32x32 tiles, k-tile 32 (R14) =================
__global__ __launch_bounds__(256) void gemmF_kernel(const float* __restrict__ B,
                                                    const float* __restrict__ bias,
                                                    float* __restrict__ Cout)
{
    const int K = HID, N = 512;
    const float* __restrict__ A = g_hid2;
    __shared__ float As[32][32];
    __shared__ float Bs[32][32];

    int t = threadIdx.x;
    int nBase = blockIdx.x * 32;
    int mBase = blockIdx.y * 32;
    int tx = t & 15, ty = t >> 4;
    int ar = t >> 3, ak = (t & 7) * 4;
    int br = t >> 3, bc = (t & 7) * 4;

    float acc00 = 0.f, acc01 = 0.f, acc10 = 0.f, acc11 = 0.f;

    float4 aP = *reinterpret_cast<const float4*>(A + (size_t)(mBase + ar) * K + ak);
    float4 bP = *reinterpret_cast<const float4*>(B + (size_t)br * N + nBase + bc);

    for (int kt = 0; kt < K; kt += 32) {
        As[ak][ar] = aP.x; As[ak + 1][ar] = aP.y; As[ak + 2][ar] = aP.z; As[ak + 3][ar] = aP.w;
        *reinterpret_cast<float4*>(&Bs[br][bc]) = bP;
        __syncthreads();
        if (kt + 32 < K) {
            aP = *reinterpret_cast<const float4*>(A + (size_t)(mBase + ar) * K + kt + 32 + ak);
            bP = *reinterpret_cast<const float4*>(B + (size_t)(kt + 32 + br) * N + nBase + bc);
        }
#pragma unroll
        for (int k = 0; k < 32; k++) {
            float a0 = As[k][ty * 2], a1 = As[k][ty * 2 + 1];
            float b0 = Bs[k][tx * 2], b1 = Bs[k][tx * 2 + 1];
            acc00 += a0 * b0; acc01 += a0 * b1;
            acc10 += a1 * b0; acc11 += a1 * b1;
        }
        __syncthreads();
    }

    int m0 = mBase + ty * 2, n0 = nBase + tx * 2;
    float bb0 = bias[n0], bb1 = bias[n0 + 1];
    Cout[(size_t)m0 * N + n0]           = acc00 + bb0;
    Cout[(size_t)m0 * N + n0 + 1]       = acc01 + bb1;
    Cout[(size_t)(m0 + 1) * N + n0]     = acc10 + bb0;
    Cout[(size_t)(m0 + 1) * N + n0 + 1] = acc11 + bb1;
}

// ================= gemm2: 128x128 tiles, B NON-duplicated (pack2 in regs) =================
template<int M, int Nact, int Npad, int K>
__global__ __launch_bounds__(256) void gemm128(const float* __restrict__ B,
                                               const float* __restrict__ bias)
{
    const float* __restrict__ A = g_hidden;
    float* __restrict__ C       = g_theta;

    __shared__ __align__(16) float As[16][128];   // [k][m]
    __shared__ __align__(16) float Bs[16][128];   // [k][n] plain floats

    int tid   = threadIdx.x;
    int nBase = blockIdx.x * 128;
    int mBase = blockIdx.y * 128;
    int tx = tid & 15;
    int ty = tid >> 4;
    int arow = tid >> 1;
    int acol = (tid & 1) * 8;
    int brow = tid >> 4;
    int bcol = (tid & 15) * 8;

    const bool nfull = (nBase + 128) <= Nact;

    ull acc[4][8];
#pragma unroll
    for (int i = 0; i < 4; i++)
#pragma unroll
        for (int j = 0; j < 8; j++) acc[i][j] = 0ull;

    float4 aP0 = *reinterpret_cast<const float4*>(A + (size_t)(mBase + arow) * K + acol);
    float4 aP1 = *reinterpret_cast<const float4*>(A + (size_t)(mBase + arow) * K + acol + 4);
    float bP[8];
    {
        const float* Brow = B + (size_t)brow * Nact + nBase + bcol;
#pragma unroll
        for (int u = 0; u < 8; u++)
            bP[u] = (nfull || (nBase + bcol + u) < Nact) ? Brow[u] : 0.f;
    }

    for (int kt = 0; kt < K; kt += 16) {
        As[acol + 0][arow] = aP0.x;
        As[acol + 1][arow] = aP0.y;
        As[acol + 2][arow] = aP0.z;
        As[acol + 3][arow] = aP0.w;
        As[acol + 4][arow] = aP1.x;
        As[acol + 5][arow] = aP1.y;
        As[acol + 6][arow] = aP1.z;
        As[acol + 7][arow] = aP1.w;
        *reinterpret_cast<float4*>(&Bs[brow][bcol])     = make_float4(bP[0], bP[1], bP[2], bP[3]);
        *reinterpret_cast<float4*>(&Bs[brow][bcol + 4]) = make_float4(bP[4], bP[5], bP[6], bP[7]);
        __syncthreads();

        if (kt + 16 < K) {
            aP0 = *reinterpret_cast<const float4*>(A + (size_t)(mBase + arow) * K + kt + 16 + acol);
            aP1 = *reinterpret_cast<const float4*>(A + (size_t)(mBase + arow) * K + kt + 16 + acol + 4);
            const float* Brow = B + (size_t)(kt + 16 + brow) * Nact + nBase + bcol;
#pragma unroll
            for (int u = 0; u < 8; u++)
                bP[u] = (nfull || (nBase + bcol + u) < Nact) ? Brow[u] : 0.f;
        }

#pragma unroll
        for (int k = 0; k < 16; k++) {
            ull ap0 = *reinterpret_cast<const ull*>(&As[k][ty * 8 + 0]);
            ull ap1 = *reinterpret_cast<const ull*>(&As[k][ty * 8 + 2]);
            ull ap2 = *reinterpret_cast<const ull*>(&As[k][ty * 8 + 4]);
            ull ap3 = *reinterpret_cast<const ull*>(&As[k][ty * 8 + 6]);
            float4 b0 = *reinterpret_cast<const float4*>(&Bs[k][tx * 8]);
            float4 b1 = *reinterpret_cast<const float4*>(&Bs[k][tx * 8 + 4]);
            float bv[8] = {b0.x, b0.y, b0.z, b0.w, b1.x, b1.y, b1.z, b1.w};
#pragma unroll
            for (int c = 0; c < 8; c++) {
                ull bd = pack2(bv[c], bv[c]);
                ffma2(acc[0][c], ap0, bd);
                ffma2(acc[1][c], ap1, bd);
                ffma2(acc[2][c], ap2, bd);
                ffma2(acc[3][c], ap3, bd);
            }
        }
        __syncthreads();
    }

#pragma unroll
    for (int rp = 0; rp < 4; rp++) {
        int m0 = mBase + ty * 8 + 2 * rp;
#pragma unroll
        for (int c = 0; c < 8; c++) {
            int n = nBase + tx * 8 + c;
            float v0, v1;
            unpack2(acc[rp][c], v0, v1);
            float bb = (n < Nact) ? bias[n] : 0.f;
            C[(size_t)m0 * Npad + n]       = v0 + bb;
            C[(size_t)(m0 + 1) * Npad + n] = v1 + bb;
        }
    }
}

// ================= cheby: 256 threads/item, register WHT (R14) =================
__global__ void __launch_bounds__(256) cheby_kernel(const float* __restrict__ Wv1,
                                                    const float* __restrict__ bv1)
{
    int b = blockIdx.x;
    int t = threadIdx.x;
    int lane = t & 31, wid = t >> 5;

    __shared__ __align__(16) float2 Cbuf[CSTR * 64];
    __shared__ __align__(16) float4 VRI[2][32];
    __shared__ float PRs[64], PIs[64];
    __shared__ float2 Jc[60];
    __shared__ float2 Hw[NOBS * 16];
    __shared__ float  qsm[16];
    __shared__ float  redf[8];

    const float* __restrict__ th = g_theta + (size_t)b * NGPAD;

    // ---- phase 1: build C[x][z] slice in registers ----
    {
        int x = t >> 2, zq = t & 3;
        float2 c[16];
        int slot0 = x * 64 + 16 * zq;
#pragma unroll
        for (int zi = 0; zi < 16; zi++) {
            int e = g_ptab.v[slot0 + zi];
            int m = e >> 2, code = e & 3;
            float tv = th[m];
            float2 v = make_float2(0.f, 0.f);
            if      (code == 0) v.x =  tv;
            else if (code == 1) v.y = -tv;
            else if (code == 2) v.x = -tv;
            else                v.y =  tv;
            c[zi] = v;
        }
        if (slot0 == 0) { c[0].x = 0.f; c[0].y = 0.f; }

#pragma unroll
        for (int st = 1; st <= 8; st <<= 1) {
#pragma unroll
            for (int i = 0; i < 16; i++) {
                if (!(i & st)) {
                    float2 a = c[i], bb = c[i + st];
                    c[i]      = make_float2(a.x + bb.x, a.y + bb.y);
                    c[i + st] = make_float2(a.x - bb.x, a.y - bb.y);
                }
            }
        }
        {
            float s = (zq & 1) ? -1.f : 1.f;
#pragma unroll
            for (int i = 0; i < 16; i++) {
                float pr = __shfl_xor_sync(0xffffffffu, c[i].x, 1);
                float pi = __shfl_xor_sync(0xffffffffu, c[i].y, 1);
                c[i].x = fmaf(s, c[i].x, pr);
                c[i].y = fmaf(s, c[i].y, pi);
            }
            s = (zq & 2) ? -1.f : 1.f;
#pragma unroll
            for (int i = 0; i < 16; i++) {
                float pr = __shfl_xor_sync(0xffffffffu, c[i].x, 2);
                float pi = __shfl_xor_sync(0xffffffffu, c[i].y, 2);
                c[i].x = fmaf(s, c[i].x, pr);
                c[i].y = fmaf(s, c[i].y, pi);
            }
        }
        float2* dst = Cbuf + x * CSTR + 16 * zq;
#pragma unroll
        for (int i = 0; i < 16; i++) dst[i] = c[i];
    }
    for (int e = t; e < NOBS * 16; e += 256) Hw[e] = g_Hw[e];
    __syncthreads();

    // ---- phase 2: extract my quarter-row; H[r][j] = C[r^j][r] ----
    int r = t >> 2, qd = t & 3;
    ull hre[8], him[8];
    float frob = 0.f;
    int jbase = 16 * qd;
#pragma unroll
    for (int j2 = 0; j2 < 8; j2++) {
        int j0 = jbase + 2 * j2;
        float2 v0 = Cbuf[(r ^ j0) * CSTR + r];
        float2 v1 = Cbuf[(r ^ (j0 + 1)) * CSTR + r];
        hre[j2] = pack2(v0.x, v1.x);
        him[j2] = pack2(v0.y, v1.y);
        frob += v0.x * v0.x + v0.y * v0.y + v1.x * v1.x + v1.y * v1.y;
    }
#pragma unroll
    for (int o = 16; o; o >>= 1) frob += __shfl_xor_sync(0xffffffffu, frob, o);
    __syncthreads();
    if (lane == 0) redf[wid] = frob;
    __syncthreads();
    float frobT = 0.f;
#pragma unroll
    for (int i = 0; i < 8; i++) frobT += redf[i];

    float lam_safe = fmaxf(1.0f, 0.31f * sqrtf(frobT) + 0.4f);
    int KC = min((int)ceilf(lam_safe) + 9, 57);

    if (t == 0) {
        float* farr = reinterpret_cast<float*>(Cbuf);
        int M = KC + 6;
        float fkp1 = 0.f, fk = 1e-12f;
        farr[M] = fk;
        float twoinv = 2.f / lam_safe;
        for (int k = M; k >= 1; k--) {
            float fkm1 = fmaf((float)k * twoinv, fk, -fkp1);
            farr[k - 1] = fkm1;
            fkp1 = fk; fk = fkm1;
        }
        float s = farr[0];
        for (int k = 2; k <= M; k += 2) s += 2.f * farr[k];
        float invs = 1.f / s;
        for (int k = 0; k <= KC; k++) {
            float J = farr[k] * invs;
            float w = (k == 0) ? 1.f : 2.f;
            float cr = 0.f, ci = 0.f;
            switch (k & 3) {
                case 0: cr =  w * J; break;
                case 1: ci =  w * J; break;
                case 2: cr = -w * J; break;
                case 3: ci = -w * J; break;
            }
            Jc[k].x = cr; Jc[k].y = ci;
        }
    }
    __syncthreads();
    float invl = 1.f / lam_safe;

    float t1r = 0.f, t1i = 0.f;
    if (qd == 0) {
        float a, b2, c, d;
        unpack2(hre[0], a, b2);
        unpack2(him[0], c, d);
        t1r = a * invl; t1i = c * invl;
        (void)b2; (void)d;
    }
    t1r = __shfl_sync(0xffffffffu, t1r, lane & ~3);
    t1i = __shfl_sync(0xffffffffu, t1i, lane & ~3);

    float tkm1r = (r == 0) ? 1.f : 0.f, tkm1i = 0.f;
    float tkr = t1r, tki = t1i;
    float2 c1 = Jc[1];
    float psr  = ((r == 0) ? Jc[0].x : 0.f) + c1.x * tkr - c1.y * tki;
    float psii = c1.x * tki + c1.y * tkr;
    int qq = r >> 1;
    int wp = 4 * (qq & 7) + (qq >> 3);
    if (qd == 0) {
        float* vf = reinterpret_cast<float*>(&VRI[0][wp]);
        vf[r & 1]       = tkr;
        vf[2 + (r & 1)] = tki;
    }
    __syncthreads();

    int cur = 0;
    float two_invl = 2.f * invl;
    for (int k = 2; k <= KC; k++) {
        const float4* Vb = VRI[cur];
        ull S1 = 0, S2 = 0, S3 = 0, S4 = 0;
#pragma unroll
        for (int j = 0; j < 8; j++) {
            float4 vv = Vb[4 * j + qd];
            ull vr = pack2(vv.x, vv.y);
            ull vi = pack2(vv.z, vv.w);
            ffma2(S1, hre[j], vr);
            ffma2(S2, him[j], vi);
            ffma2(S3, hre[j], vi);
            ffma2(S4, him[j], vr);
        }
        float a, b2, c, d;
        unpack2(S1, a, b2); float s1 = a + b2;
        unpack2(S2, a, b2); float s2 = a + b2;
        unpack2(S3, a, b2); float s3 = a + b2;
        unpack2(S4, a, b2); float s4 = a + b2;
        float wr = s1 - s2, wi = s3 + s4;
        wr += __shfl_xor_sync(0xffffffffu, wr, 1);
        wi += __shfl_xor_sync(0xffffffffu, wi, 1);
        wr += __shfl_xor_sync(0xffffffffu, wr, 2);
        wi += __shfl_xor_sync(0xffffffffu, wi, 2);

        float tnr = fmaf(two_invl, wr, -tkm1r);
        float tni = fmaf(two_invl, wi, -tkm1i);
        float2 cc = Jc[k];
        psr  += cc.x * tnr - cc.y * tni;
        psii += cc.x * tni + cc.y * tnr;
        tkm1r = tkr; tkm1i = tki;
        tkr = tnr;   tki = tni;
        if (qd == 0) {
            float* vf = reinterpret_cast<float*>(&VRI[cur ^ 1][wp]);
            vf[r & 1]       = tnr;
            vf[2 + (r & 1)] = tni;
        }
        __syncthreads();
        cur ^= 1;
    }

    if (qd == 0) { PRs[r] = psr; PIs[r] = psii; }
    __syncthreads();

    float qr = 0.f;
    if (t < 60) {
        int w = t >> 2, rbase = (t & 3) * 4;
        int a = cPA[w], bq = cPB[w];
        int pa = 5 - a, pb = 5 - bq;
        for (int rr = 0; rr < 4; rr++) {
            int rj = rbase + rr;
            int ibase = 0, bitidx = 3;
#pragma unroll
            for (int q = 0; q < 6; q++) {
                if (q == a || q == bq) continue;
                ibase |= ((rj >> bitidx) & 1) << (5 - q);
                bitidx--;
            }
            float2 v[4];
#pragma unroll
            for (int k = 0; k < 4; k++) {
                int i = ibase | ((k >> 1) << pa) | ((k & 1) << pb);
                v[k] = make_float2(PRs[i], PIs[i]);
            }
#pragma unroll
            for (int li = 0; li < 4; li++)
#pragma unroll
                for (int k = 0; k < 4; k++) {
                    float2 hw = Hw[w * 16 + li * 4 + k];
                    float pr = v[li].x * v[k].x + v[li].y * v[k].y;
                    float pi = v[li].x * v[k].y - v[li].y * v[k].x;
                    qr += hw.x * pr - hw.y * pi;
                }
        }
    }
    qr += __shfl_down_sync(0xffffffffu, qr, 1);
    qr += __shfl_down_sync(0xffffffffu, qr, 2);
    if (t < 60 && (t & 3) == 0) qsm[t >> 2] = qr;
    __syncthreads();

    {
        int col = t;
        float acc = bv1[col];
#pragma unroll
        for (int w = 0; w < NOBS; w++) acc = fmaf(qsm[w], Wv1[w * HID + col], acc);
        g_hid2[(size_t)b * HID + col] = acc / (1.f + expf(-acc));
    }
}

// ---------------- launch ----------------
extern "C" void kernel_launch(void* const* d_in, const int* in_sizes, int n_in,
                              void* d_out, int out_size)
{
    const float* x    = (const float*)d_in[0];
    const float* W1   = (const float*)d_in[1];
    const float* b1   = (const float*)d_in[2];
    const float* W2   = (const float*)d_in[3];
    const float* b2   = (const float*)d_in[4];
    const float* Aoff = (const float*)d_in[5];
    const float* Boff = (const float*)d_in[6];
    const float* Ddia = (const float*)d_in[7];
    const float* Wv1  = (const float*)d_in[8];
    const float* bv1  = (const float*)d_in[9];
    const float* Wv2  = (const float*)d_in[10];
    const float* bv2  = (const float*)d_in[11];
    float* out = (float*)d_out;

    // slots 1-2: prep twice (idempotent) -> gemm128 lands in profiled slot 4
    prep_kernel<<<1, 256>>>(Aoff, Boff, Ddia);
    prep_kernel<<<1, 256>>>(Aoff, Boff, Ddia);
    // slot 3: hidden = silu(x @ W1 + b1)
    gemm1_kernel<<<dim3(HID / 32, BATCH / 32), 256>>>(x, W1, b1);
    // slot 4: theta = hidden @ W2 + b2  (PROFILED) — 128x128, B non-dup
    gemm128<BATCH, NGEN, NGPAD, HID><<<dim3(NGPAD / 128, BATCH / 128), 256>>>(W2, b2);
    // slot 5: psi/observables/hidden2
    cheby_kernel<<<BATCH, 256>>>(Wv1, bv1);
    // slot 6: out = hid2 @ Wv2 + bv2
    gemmF_kernel<<<dim3(512 / 32, BATCH / 32), 256>>>(Wv2, bv2, out);
}